// round 13
// baseline (speedup 1.0000x reference)
#include <cuda_runtime.h>
#include <cuda_fp16.h>
#include <math.h>
#include <stdint.h>

#define M_DIM 8192
#define H_DIM 4096
#define I_DIM 11008

// Fragment-packed f16 operands.
// A-pack: [mTile16][kTile16][lane32][8 halves]  (PTX m16n8k16 A frag: a0,a1,a2,a3)
// B-pack: [nTile8][kTile16][lane32][4 halves]   (PTX m16n8k16 B frag: b0,b1)
__device__ unsigned short g_xp [(size_t)M_DIM * H_DIM];   // x  A-pack (K=H)
__device__ unsigned short g_wgp[(size_t)I_DIM * H_DIM];   // wg^T B-pack
__device__ unsigned short g_wup[(size_t)I_DIM * H_DIM];   // wu^T B-pack
__device__ unsigned short g_wdp[(size_t)H_DIM * I_DIM];   // wd^T B-pack
__device__ unsigned short g_hp [(size_t)M_DIM * I_DIM];   // h  A-pack (K=I)

__device__ __forceinline__ uint32_t pkh(float a, float b) {
    __half2 h = __floats2half2_rn(a, b);   // low = a, high = b
    return *(uint32_t*)&h;
}
__device__ __forceinline__ void mma_f16(float* c, uint32_t a0, uint32_t a1, uint32_t a2,
                                        uint32_t a3, uint32_t b0, uint32_t b1) {
    asm volatile(
        "mma.sync.aligned.m16n8k16.row.col.f32.f16.f16.f32 "
        "{%0,%1,%2,%3}, {%4,%5,%6,%7}, {%8,%9}, {%0,%1,%2,%3};"
        : "+f"(c[0]), "+f"(c[1]), "+f"(c[2]), "+f"(c[3])
        : "r"(a0), "r"(a1), "r"(a2), "r"(a3), "r"(b0), "r"(b1));
}
__device__ __forceinline__ uint32_t smem_u32(const void* p) {
    uint32_t a;
    asm("{ .reg .u64 t; cvta.to.shared.u64 t, %1; cvt.u32.u64 %0, t; }" : "=r"(a) : "l"(p));
    return a;
}
__device__ __forceinline__ void cpa(uint32_t dst, const void* src) {
    asm volatile("cp.async.cg.shared.global [%0], [%1], 16;" :: "r"(dst), "l"(src));
}
#define CP_COMMIT() asm volatile("cp.async.commit_group;" ::: "memory")
#define CP_WAIT(n)  asm volatile("cp.async.wait_group %0;" :: "n"(n) : "memory")

// stage (BK=64, BM=256): A 64 tiles (16mt x 4kt) x 512B = 32KB,
//                        B 64 tiles (16 slots x 4kt) x 256B = 16KB
#define A_BYTES 32768
#define STAGE 49152
#define NSTG 3
#define SMEM_BYTES (NSTG * STAGE)   // 147456 -> 1 CTA/SM, 16 warps
#define NTHR 512

// ---------------------------------------------------------------------------
// Convert kernels (once per call; DRAM-bound, ~190us total)
// ---------------------------------------------------------------------------
__global__ __launch_bounds__(256)
void k_cvt_xA(const float* __restrict__ x)
{
    long long g = (long long)blockIdx.x * 256 + threadIdx.x;
    long long tile = g >> 5;
    int lane = (int)(g & 31);
    const int K16 = H_DIM / 16;
    int mt = (int)(tile / K16), kt = (int)(tile % K16);
    long long r = mt * 16 + (lane >> 2);
    int k = kt * 16 + (lane & 3) * 2;
    float2 v00 = *(const float2*)(x + r * H_DIM + k);
    float2 v01 = *(const float2*)(x + r * H_DIM + k + 8);
    float2 v10 = *(const float2*)(x + (r + 8) * H_DIM + k);
    float2 v11 = *(const float2*)(x + (r + 8) * H_DIM + k + 8);
    uint4 o;
    o.x = pkh(v00.x, v00.y);
    o.y = pkh(v10.x, v10.y);
    o.z = pkh(v01.x, v01.y);
    o.w = pkh(v11.x, v11.y);
    *(uint4*)&g_xp[tile * 256 + lane * 8] = o;
}

// w [K,N] row-major -> B-pack [N/8][K/16][lane][2 b32]; block 16k x 64n
__global__ __launch_bounds__(256)
void k_cvt_wB(const float* __restrict__ w, unsigned short* __restrict__ dst, int K, int N)
{
    __shared__ float ts[16][72];
    const int t = threadIdx.x;
    const int k0 = blockIdx.x * 16, n0 = blockIdx.y * 64;
    const int K16 = K / 16;
#pragma unroll
    for (int j = 0; j < 4; j++) {
        int idx = j * 256 + t, kk = idx >> 6, nn = idx & 63;
        ts[kk][nn] = w[(long long)(k0 + kk) * N + n0 + nn];
    }
    __syncthreads();
    const int nt = t >> 5, lane = t & 31;
    const int c2 = (lane & 3) * 2, n = nt * 8 + (lane >> 2);
    uint2 o;
    o.x = pkh(ts[c2][n],     ts[c2 + 1][n]);
    o.y = pkh(ts[c2 + 8][n], ts[c2 + 9][n]);
    long long base = ((long long)((n0 >> 3) + nt) * K16 + blockIdx.x) * 128 + lane * 4;
    *(uint2*)&dst[base] = o;
}

// ---------------------------------------------------------------------------
// GEMM1: h = silu(x@wg)*(x@wu). CTA 256m x 64n (gate+up), BK=64. KT=64.
// 512 thr, warps 8m x 2n; warp: 32m x 32n gate + 32n up.
// ---------------------------------------------------------------------------
__global__ __launch_bounds__(NTHR, 1)
void k_gateup()
{
    extern __shared__ char smp[];
    const uint32_t sbase = smem_u32(smp);

    const int t = threadIdx.x, lane = t & 31, wid = t >> 5;
    const int wm = wid & 7, wn = wid >> 3;

    const int num_pid_m = M_DIM / 256, num_pid_n = I_DIM / 64, GROUP = 8;
    int pid = blockIdx.x;
    int gsz = GROUP * num_pid_n;
    int gid = pid / gsz;
    int first = gid * GROUP;
    int gm = min(GROUP, num_pid_m - first);
    int pid_m = first + (pid % gm);
    int pid_n = (pid % gsz) / gm;
    const int m0 = pid_m * 256, n0 = pid_n * 64;

    const int K16 = H_DIM / 16;
    const int mtile0 = m0 >> 4, ntile0 = n0 >> 3;

    float acc[2][8][4];   // n8 0-3 gate, 4-7 up
#pragma unroll
    for (int i = 0; i < 2; i++)
#pragma unroll
        for (int j = 0; j < 8; j++)
#pragma unroll
            for (int k = 0; k < 4; k++) acc[i][j][k] = 0.f;

    const int KT = H_DIM / 64;   // 64

    auto issue = [&](int kt, int st) {
        const uint32_t sA = sbase + (uint32_t)st * STAGE;
        const int ktb = kt * 4;
#pragma unroll
        for (int j = 0; j < 4; j++) {   // A: 2048 16B chunks
            int c = j * NTHR + t;
            int tile = c >> 5, ch = c & 31;
            int mtl = tile >> 2, ktl = tile & 3;
            cpa(sA + tile * 512 + ch * 16,
                g_xp + ((long long)(mtile0 + mtl) * K16 + ktb + ktl) * 256 + ch * 8);
        }
#pragma unroll
        for (int j = 0; j < 2; j++) {   // B: 1024 16B chunks (64 tiles x 16)
            int c = j * NTHR + t;
            int tile = c >> 4, ch = c & 15;
            int slot = tile >> 2, ktl = tile & 3;
            const unsigned short* W = (slot < 8) ? g_wgp : g_wup;
            int ntl = slot & 7;
            cpa(sA + A_BYTES + tile * 256 + ch * 16,
                W + ((long long)(ntile0 + ntl) * K16 + ktb + ktl) * 128 + ch * 8);
        }
    };

    issue(0, 0); CP_COMMIT();
    issue(1, 1); CP_COMMIT();

    int sc = 0;
    for (int kt = 0; kt < KT; ++kt) {
        CP_WAIT(1);
        __syncthreads();
        if (kt + 2 < KT) {
            int sn = sc + 2; if (sn >= NSTG) sn -= NSTG;
            issue(kt + 2, sn);
        }
        CP_COMMIT();

        const char* sp = smp + sc * STAGE;
#pragma unroll
        for (int ks = 0; ks < 4; ks++) {
            uint4 a[2];
#pragma unroll
            for (int mt = 0; mt < 2; mt++)
                a[mt] = *(const uint4*)(sp + ((wm * 2 + mt) * 4 + ks) * 512 + lane * 16);
#pragma unroll
            for (int n8 = 0; n8 < 8; n8++) {
                int slot = (n8 >> 2) * 8 + wn * 4 + (n8 & 3);
                uint2 b = *(const uint2*)(sp + A_BYTES + (slot * 4 + ks) * 256 + lane * 8);
#pragma unroll
                for (int mt = 0; mt < 2; mt++)
                    mma_f16(acc[mt][n8], a[mt].x, a[mt].y, a[mt].z, a[mt].w, b.x, b.y);
            }
        }
        sc = sc + 1; if (sc >= NSTG) sc -= NSTG;
    }

    // Epilogue: h = silu(g)*u; repack to f16 A-pack via per-warp smem staging.
    __syncthreads();   // pipeline smem reuse (16 warps x 4KB = 64KB < 144KB)
    {
        float* buf = (float*)(smp + wid * 4096);   // [2 mt][16 r][32 c]
        const int r0 = lane >> 2, c0 = (lane & 3) * 2;
#pragma unroll
        for (int mt = 0; mt < 2; mt++) {
#pragma unroll
            for (int p = 0; p < 4; p++) {
                int col = p * 8 + c0;
                float g0 = acc[mt][p][0], u0 = acc[mt][p + 4][0];
                float g1 = acc[mt][p][1], u1 = acc[mt][p + 4][1];
                float g2 = acc[mt][p][2], u2 = acc[mt][p + 4][2];
                float g3 = acc[mt][p][3], u3 = acc[mt][p + 4][3];
                float h0 = g0 / (1.f + __expf(-g0)) * u0;
                float h1 = g1 / (1.f + __expf(-g1)) * u1;
                float h2 = g2 / (1.f + __expf(-g2)) * u2;
                float h3 = g3 / (1.f + __expf(-g3)) * u3;
                *(float2*)&buf[(mt * 16 + r0) * 32 + col]     = make_float2(h0, h1);
                *(float2*)&buf[(mt * 16 + r0 + 8) * 32 + col] = make_float2(h2, h3);
            }
        }
        __syncwarp();
        const int I16 = I_DIM / 16;
#pragma unroll
        for (int mt = 0; mt < 2; mt++) {
#pragma unroll
            for (int kt2 = 0; kt2 < 2; kt2++) {
                const float* tb = &buf[mt * 16 * 32];
                int r = lane >> 2, c = (lane & 3) * 2 + kt2 * 16;
                uint4 o;
                o.x = pkh(tb[r * 32 + c],           tb[r * 32 + c + 1]);
                o.y = pkh(tb[(r + 8) * 32 + c],     tb[(r + 8) * 32 + c + 1]);
                o.z = pkh(tb[r * 32 + c + 8],       tb[r * 32 + c + 9]);
                o.w = pkh(tb[(r + 8) * 32 + c + 8], tb[(r + 8) * 32 + c + 9]);
                long long Mt = (m0 + wm * 32 + mt * 16) >> 4;
                long long Kt = (n0 + wn * 32 + kt2 * 16) >> 4;
                *(uint4*)&g_hp[(Mt * I16 + Kt) * 256 + lane * 8] = o;
            }
        }
    }
}

// ---------------------------------------------------------------------------
// GEMM2: y = h @ wd. CTA 256m x 128n, BK=64, warp tile 32m x 64n. KT=172.
// 512 thr, warps 8m x 2n.
// ---------------------------------------------------------------------------
__global__ __launch_bounds__(NTHR, 1)
void k_down(float* __restrict__ y)
{
    extern __shared__ char smp[];
    const uint32_t sbase = smem_u32(smp);

    const int t = threadIdx.x, lane = t & 31, wid = t >> 5;
    const int wm = wid & 7, wn = wid >> 3;

    const int num_pid_m = M_DIM / 256, num_pid_n = H_DIM / 128, GROUP = 8;
    int pid = blockIdx.x;
    int gsz = GROUP * num_pid_n;
    int gid = pid / gsz;
    int first = gid * GROUP;
    int gm = min(GROUP, num_pid_m - first);
    int pid_m = first + (pid % gm);
    int pid_n = (pid % gsz) / gm;
    const int m0 = pid_m * 256, n0 = pid_n * 128;

    const int K16 = I_DIM / 16;
    const int mtile0 = m0 >> 4, ntile0 = n0 >> 3;

    float acc[2][8][4];
#pragma unroll
    for (int i = 0; i < 2; i++)
#pragma unroll
        for (int j = 0; j < 8; j++)
#pragma unroll
            for (int k = 0; k < 4; k++) acc[i][j][k] = 0.f;

    const int KT = I_DIM / 64;   // 172

    auto issue = [&](int kt, int st) {
        const uint32_t sA = sbase + (uint32_t)st * STAGE;
        const int ktb = kt * 4;
#pragma unroll
        for (int j = 0; j < 4; j++) {   // A: 2048 chunks
            int c = j * NTHR + t;
            int tile = c >> 5, ch = c & 31;
            int mtl = tile >> 2, ktl = tile & 3;
            cpa(sA + tile * 512 + ch * 16,
                g_hp + ((long long)(mtile0 + mtl) * K16 + ktb + ktl) * 256 + ch * 8);
        }
#pragma unroll
        for (int j = 0; j < 2; j++) {   // B: 1024 chunks (64 tiles: 16 ntl x 4 kt)
            int c = j * NTHR + t;
            int tile = c >> 4, ch = c & 15;
            int ntl = tile >> 2, ktl = tile & 3;
            cpa(sA + A_BYTES + tile * 256 + ch * 16,
                g_wdp + ((long long)(ntile0 + ntl) * K16 + ktb + ktl) * 128 + ch * 8);
        }
    };

    issue(0, 0); CP_COMMIT();
    issue(1, 1); CP_COMMIT();

    int sc = 0;
    for (int kt = 0; kt < KT; ++kt) {
        CP_WAIT(1);
        __syncthreads();
        if (kt + 2 < KT) {
            int sn = sc + 2; if (sn >= NSTG) sn -= NSTG;
            issue(kt + 2, sn);
        }
        CP_COMMIT();

        const char* sp = smp + sc * STAGE;
#pragma unroll
        for (int ks = 0; ks < 4; ks++) {
            uint4 a[2];
#pragma unroll
            for (int mt = 0; mt < 2; mt++)
                a[mt] = *(const uint4*)(sp + ((wm * 2 + mt) * 4 + ks) * 512 + lane * 16);
#pragma unroll
            for (int n8 = 0; n8 < 8; n8++) {
                int slot = wn * 8 + n8;
                uint2 b = *(const uint2*)(sp + A_BYTES + (slot * 4 + ks) * 256 + lane * 8);
#pragma unroll
                for (int mt = 0; mt < 2; mt++)
                    mma_f16(acc[mt][n8], a[mt].x, a[mt].y, a[mt].z, a[mt].w, b.x, b.y);
            }
        }
        sc = sc + 1; if (sc >= NSTG) sc -= NSTG;
    }

#pragma unroll
    for (int mt = 0; mt < 2; mt++) {
#pragma unroll
        for (int n8 = 0; n8 < 8; n8++) {
            int row = m0 + wm * 32 + mt * 16 + (lane >> 2);
            int col = n0 + wn * 64 + n8 * 8 + (lane & 3) * 2;
#pragma unroll
            for (int half = 0; half < 2; half++) {
                int r = row + half * 8;
                float2 o = make_float2(acc[mt][n8][half * 2], acc[mt][n8][half * 2 + 1]);
                *(float2*)(y + (long long)r * H_DIM + col) = o;
            }
        }
    }
}

// ---------------------------------------------------------------------------
extern "C" void kernel_launch(void* const* d_in, const int* in_sizes, int n_in,
                              void* d_out, int out_size)
{
    const float* x  = (const float*)d_in[0];
    const float* wg = (const float*)d_in[1];
    const float* wu = (const float*)d_in[2];
    const float* wd = (const float*)d_in[3];
    float* y = (float*)d_out;

    cudaFuncSetAttribute(k_gateup, cudaFuncAttributeMaxDynamicSharedMemorySize, SMEM_BYTES);
    cudaFuncSetAttribute(k_down,   cudaFuncAttributeMaxDynamicSharedMemorySize, SMEM_BYTES);

    unsigned short *wgp, *wup, *wdp;
    cudaGetSymbolAddress((void**)&wgp, g_wgp);
    cudaGetSymbolAddress((void**)&wup, g_wup);
    cudaGetSymbolAddress((void**)&wdp, g_wdp);

    k_cvt_xA<<<(int)(((long long)(M_DIM / 16) * (H_DIM / 16) * 32) / 256), 256>>>(x);
    k_cvt_wB<<<dim3(H_DIM / 16, I_DIM / 64), 256>>>(wg, wgp, H_DIM, I_DIM);
    k_cvt_wB<<<dim3(H_DIM / 16, I_DIM / 64), 256>>>(wu, wup, H_DIM, I_DIM);
    k_cvt_wB<<<dim3(I_DIM / 16, H_DIM / 64), 256>>>(wd, wdp, I_DIM, H_DIM);

    const int grid1 = (M_DIM / 256) * (I_DIM / 64);    // 32 * 172 = 5504
    const int grid2 = (M_DIM / 256) * (H_DIM / 128);   // 32 * 32  = 1024
    k_gateup<<<grid1, NTHR, SMEM_BYTES>>>();
    k_down<<<grid2, NTHR, SMEM_BYTES>>>(y);
}

// round 14
// speedup vs baseline: 1.0952x; 1.0952x over previous
#include <cuda_runtime.h>
#include <cuda_fp16.h>
#include <math.h>
#include <stdint.h>

#define M_DIM 8192
#define H_DIM 4096
#define I_DIM 11008

// Fragment-packed f16 operands.
// A-pack: [mTile16][kTile16][lane32][8 halves]  (PTX m16n8k16 A frag: a0,a1,a2,a3)
// B-pack: [nTile8][kTile16][lane32][4 halves]   (PTX m16n8k16 B frag: b0,b1)
__device__ unsigned short g_xp [(size_t)M_DIM * H_DIM];   // x  A-pack (K=H)
__device__ unsigned short g_wgp[(size_t)I_DIM * H_DIM];   // wg^T B-pack
__device__ unsigned short g_wup[(size_t)I_DIM * H_DIM];   // wu^T B-pack
__device__ unsigned short g_wdp[(size_t)H_DIM * I_DIM];   // wd^T B-pack
__device__ unsigned short g_hp [(size_t)M_DIM * I_DIM];   // h  A-pack (K=I)

__device__ __forceinline__ uint32_t pkh(float a, float b) {
    __half2 h = __floats2half2_rn(a, b);   // low = a, high = b
    return *(uint32_t*)&h;
}
__device__ __forceinline__ void mma_f16(float* c, uint32_t a0, uint32_t a1, uint32_t a2,
                                        uint32_t a3, uint32_t b0, uint32_t b1) {
    asm volatile(
        "mma.sync.aligned.m16n8k16.row.col.f32.f16.f16.f32 "
        "{%0,%1,%2,%3}, {%4,%5,%6,%7}, {%8,%9}, {%0,%1,%2,%3};"
        : "+f"(c[0]), "+f"(c[1]), "+f"(c[2]), "+f"(c[3])
        : "r"(a0), "r"(a1), "r"(a2), "r"(a3), "r"(b0), "r"(b1));
}
__device__ __forceinline__ uint32_t smem_u32(const void* p) {
    uint32_t a;
    asm("{ .reg .u64 t; cvta.to.shared.u64 t, %1; cvt.u32.u64 %0, t; }" : "=r"(a) : "l"(p));
    return a;
}
__device__ __forceinline__ void cpa(uint32_t dst, const void* src) {
    asm volatile("cp.async.cg.shared.global [%0], [%1], 16;" :: "r"(dst), "l"(src));
}
#define CP_COMMIT() asm volatile("cp.async.commit_group;" ::: "memory")
#define CP_WAIT(n)  asm volatile("cp.async.wait_group %0;" :: "n"(n) : "memory")

// stage: A 32 tiles (8mt x 4kt) x 512B = 16KB, B 64 tiles x 256B = 16KB. BK=64.
#define A_BYTES 16384
#define STAGE 32768
#define NSTG 3
#define SMEM_BYTES (NSTG * STAGE)   // 98304

// ---------------------------------------------------------------------------
// Convert kernels (once per call; DRAM-bound)
// ---------------------------------------------------------------------------
// x [M,K] row-major -> f16 A-pack
__global__ __launch_bounds__(256)
void k_cvt_xA(const float* __restrict__ x)
{
    long long g = (long long)blockIdx.x * 256 + threadIdx.x;
    long long tile = g >> 5;
    int lane = (int)(g & 31);
    const int K16 = H_DIM / 16;
    int mt = (int)(tile / K16), kt = (int)(tile % K16);
    long long r = mt * 16 + (lane >> 2);
    int k = kt * 16 + (lane & 3) * 2;
    float2 v00 = *(const float2*)(x + r * H_DIM + k);
    float2 v01 = *(const float2*)(x + r * H_DIM + k + 8);
    float2 v10 = *(const float2*)(x + (r + 8) * H_DIM + k);
    float2 v11 = *(const float2*)(x + (r + 8) * H_DIM + k + 8);
    uint4 o;
    o.x = pkh(v00.x, v00.y);   // a0
    o.y = pkh(v10.x, v10.y);   // a1
    o.z = pkh(v01.x, v01.y);   // a2
    o.w = pkh(v11.x, v11.y);   // a3
    *(uint4*)&g_xp[tile * 256 + lane * 8] = o;
}

// gate+up combined: w [K,N] row-major -> B-pack [N/8][K/16][lane][2 b32]
// block 16k x 64n; blockIdx.z selects (wg -> g_wgp) or (wu -> g_wup).
__global__ __launch_bounds__(256)
void k_cvt_wgu(const float* __restrict__ wg, const float* __restrict__ wu)
{
    __shared__ float ts[16][72];
    const int t = threadIdx.x;
    const int k0 = blockIdx.x * 16, n0 = blockIdx.y * 64;
    const int K16 = H_DIM / 16;
    const float* w = blockIdx.z ? wu : wg;
    unsigned short* dst = blockIdx.z ? g_wup : g_wgp;

    // vectorized load: 16 rows x 64 cols = 256 float4, one per thread
    {
        int row = t >> 4, c4 = t & 15;
        float4 v = *(const float4*)(w + (long long)(k0 + row) * I_DIM + n0 + c4 * 4);
        ts[row][c4 * 4 + 0] = v.x;
        ts[row][c4 * 4 + 1] = v.y;
        ts[row][c4 * 4 + 2] = v.z;
        ts[row][c4 * 4 + 3] = v.w;
    }
    __syncthreads();
    const int nt = t >> 5, lane = t & 31;
    const int c2 = (lane & 3) * 2, n = nt * 8 + (lane >> 2);
    uint2 o;
    o.x = pkh(ts[c2][n],     ts[c2 + 1][n]);
    o.y = pkh(ts[c2 + 8][n], ts[c2 + 9][n]);
    long long base = ((long long)((n0 >> 3) + nt) * K16 + blockIdx.x) * 128 + lane * 4;
    *(uint2*)&dst[base] = o;
}

// wd: [K=I, N=H] -> B-pack
__global__ __launch_bounds__(256)
void k_cvt_wd(const float* __restrict__ w)
{
    __shared__ float ts[16][72];
    const int t = threadIdx.x;
    const int k0 = blockIdx.x * 16, n0 = blockIdx.y * 64;
    const int K16 = I_DIM / 16;
    {
        int row = t >> 4, c4 = t & 15;
        float4 v = *(const float4*)(w + (long long)(k0 + row) * H_DIM + n0 + c4 * 4);
        ts[row][c4 * 4 + 0] = v.x;
        ts[row][c4 * 4 + 1] = v.y;
        ts[row][c4 * 4 + 2] = v.z;
        ts[row][c4 * 4 + 3] = v.w;
    }
    __syncthreads();
    const int nt = t >> 5, lane = t & 31;
    const int c2 = (lane & 3) * 2, n = nt * 8 + (lane >> 2);
    uint2 o;
    o.x = pkh(ts[c2][n],     ts[c2 + 1][n]);
    o.y = pkh(ts[c2 + 8][n], ts[c2 + 9][n]);
    long long base = ((long long)((n0 >> 3) + nt) * K16 + blockIdx.x) * 128 + lane * 4;
    *(uint2*)&g_wdp[base] = o;
}

// ---------------------------------------------------------------------------
// GEMM1: h = silu(x@wg)*(x@wu). CTA 128m x 64n (gate+up), BK=64. KT=64.
// 256 thr, warps 4m x 2n; warp: 32m x 32n gate + 32n up.  (R12 mainloop)
// ---------------------------------------------------------------------------
__global__ __launch_bounds__(256, 2)
void k_gateup()
{
    extern __shared__ char smp[];
    const uint32_t sbase = smem_u32(smp);

    const int t = threadIdx.x, lane = t & 31, wid = t >> 5;
    const int wm = wid & 3, wn = wid >> 2;

    const int num_pid_m = M_DIM / 128, num_pid_n = I_DIM / 64, GROUP = 16;
    int pid = blockIdx.x;
    int gsz = GROUP * num_pid_n;
    int gid = pid / gsz;
    int first = gid * GROUP;
    int gm = min(GROUP, num_pid_m - first);
    int pid_m = first + (pid % gm);
    int pid_n = (pid % gsz) / gm;
    const int m0 = pid_m * 128, n0 = pid_n * 64;

    const int K16 = H_DIM / 16;
    const int mtile0 = m0 >> 4, ntile0 = n0 >> 3;

    float acc[2][8][4];   // n8 0-3 gate, 4-7 up
#pragma unroll
    for (int i = 0; i < 2; i++)
#pragma unroll
        for (int j = 0; j < 8; j++)
#pragma unroll
            for (int k = 0; k < 4; k++) acc[i][j][k] = 0.f;

    const int KT = H_DIM / 64;   // 64

    auto issue = [&](int kt, int st) {
        const uint32_t sA = sbase + (uint32_t)st * STAGE;
        const int ktb = kt * 4;
#pragma unroll
        for (int j = 0; j < 4; j++) {   // A: 1024 16B chunks
            int c = j * 256 + t;
            int tile = c >> 5, ch = c & 31;
            int mtl = tile >> 2, ktl = tile & 3;
            cpa(sA + tile * 512 + ch * 16,
                g_xp + ((long long)(mtile0 + mtl) * K16 + ktb + ktl) * 256 + ch * 8);
        }
#pragma unroll
        for (int j = 0; j < 4; j++) {   // B: 1024 16B chunks (64 tiles x 16)
            int c = j * 256 + t;
            int tile = c >> 4, ch = c & 15;
            int slot = tile >> 2, ktl = tile & 3;
            const unsigned short* W = (slot < 8) ? g_wgp : g_wup;
            int ntl = slot & 7;
            cpa(sA + A_BYTES + tile * 256 + ch * 16,
                W + ((long long)(ntile0 + ntl) * K16 + ktb + ktl) * 128 + ch * 8);
        }
    };

    issue(0, 0); CP_COMMIT();
    issue(1, 1); CP_COMMIT();

    int sc = 0;
    for (int kt = 0; kt < KT; ++kt) {
        CP_WAIT(1);
        __syncthreads();
        if (kt + 2 < KT) {
            int sn = sc + 2; if (sn >= NSTG) sn -= NSTG;
            issue(kt + 2, sn);
        }
        CP_COMMIT();

        const char* sp = smp + sc * STAGE;
#pragma unroll
        for (int ks = 0; ks < 4; ks++) {
            uint4 a[2];
#pragma unroll
            for (int mt = 0; mt < 2; mt++)
                a[mt] = *(const uint4*)(sp + ((wm * 2 + mt) * 4 + ks) * 512 + lane * 16);
#pragma unroll
            for (int n8 = 0; n8 < 8; n8++) {
                int slot = (n8 >> 2) * 8 + wn * 4 + (n8 & 3);
                uint2 b = *(const uint2*)(sp + A_BYTES + (slot * 4 + ks) * 256 + lane * 8);
#pragma unroll
                for (int mt = 0; mt < 2; mt++)
                    mma_f16(acc[mt][n8], a[mt].x, a[mt].y, a[mt].z, a[mt].w, b.x, b.y);
            }
        }
        sc = sc + 1; if (sc >= NSTG) sc -= NSTG;
    }

    // Epilogue: h = silu(g)*u; repack to f16 A-pack via per-warp smem staging.
    __syncthreads();
    {
        float* buf = (float*)(smp + wid * 4096);   // [2 mt][16 r][32 c]
        const int r0 = lane >> 2, c0 = (lane & 3) * 2;
#pragma unroll
        for (int mt = 0; mt < 2; mt++) {
#pragma unroll
            for (int p = 0; p < 4; p++) {
                int col = p * 8 + c0;
                float g0 = acc[mt][p][0], u0 = acc[mt][p + 4][0];
                float g1 = acc[mt][p][1], u1 = acc[mt][p + 4][1];
                float g2 = acc[mt][p][2], u2 = acc[mt][p + 4][2];
                float g3 = acc[mt][p][3], u3 = acc[mt][p + 4][3];
                float h0 = g0 / (1.f + __expf(-g0)) * u0;
                float h1 = g1 / (1.f + __expf(-g1)) * u1;
                float h2 = g2 / (1.f + __expf(-g2)) * u2;
                float h3 = g3 / (1.f + __expf(-g3)) * u3;
                *(float2*)&buf[(mt * 16 + r0) * 32 + col]     = make_float2(h0, h1);
                *(float2*)&buf[(mt * 16 + r0 + 8) * 32 + col] = make_float2(h2, h3);
            }
        }
        __syncwarp();
        const int I16 = I_DIM / 16;
#pragma unroll
        for (int mt = 0; mt < 2; mt++) {
#pragma unroll
            for (int kt2 = 0; kt2 < 2; kt2++) {
                const float* tb = &buf[mt * 16 * 32];
                int r = lane >> 2, c = (lane & 3) * 2 + kt2 * 16;
                uint4 o;
                o.x = pkh(tb[r * 32 + c],           tb[r * 32 + c + 1]);
                o.y = pkh(tb[(r + 8) * 32 + c],     tb[(r + 8) * 32 + c + 1]);
                o.z = pkh(tb[r * 32 + c + 8],       tb[r * 32 + c + 9]);
                o.w = pkh(tb[(r + 8) * 32 + c + 8], tb[(r + 8) * 32 + c + 9]);
                long long Mt = (m0 + wm * 32 + mt * 16) >> 4;
                long long Kt = (n0 + wn * 32 + kt2 * 16) >> 4;
                *(uint4*)&g_hp[(Mt * I16 + Kt) * 256 + lane * 8] = o;
            }
        }
    }
}

// ---------------------------------------------------------------------------
// GEMM2: y = h @ wd. CTA 128m x 128n, BK=64, warp tile 32m x 64n. KT=172.
// ---------------------------------------------------------------------------
__global__ __launch_bounds__(256, 2)
void k_down(float* __restrict__ y)
{
    extern __shared__ char smp[];
    const uint32_t sbase = smem_u32(smp);

    const int t = threadIdx.x, lane = t & 31, wid = t >> 5;
    const int wm = wid & 3, wn = wid >> 2;

    const int num_pid_m = M_DIM / 128, num_pid_n = H_DIM / 128, GROUP = 16;
    int pid = blockIdx.x;
    int gsz = GROUP * num_pid_n;
    int gid = pid / gsz;
    int first = gid * GROUP;
    int gm = min(GROUP, num_pid_m - first);
    int pid_m = first + (pid % gm);
    int pid_n = (pid % gsz) / gm;
    const int m0 = pid_m * 128, n0 = pid_n * 128;

    const int K16 = I_DIM / 16;
    const int mtile0 = m0 >> 4, ntile0 = n0 >> 3;

    float acc[2][8][4];
#pragma unroll
    for (int i = 0; i < 2; i++)
#pragma unroll
        for (int j = 0; j < 8; j++)
#pragma unroll
            for (int k = 0; k < 4; k++) acc[i][j][k] = 0.f;

    const int KT = I_DIM / 64;   // 172

    auto issue = [&](int kt, int st) {
        const uint32_t sA = sbase + (uint32_t)st * STAGE;
        const int ktb = kt * 4;
#pragma unroll
        for (int j = 0; j < 4; j++) {
            int c = j * 256 + t;
            int tile = c >> 5, ch = c & 31;
            int mtl = tile >> 2, ktl = tile & 3;
            cpa(sA + tile * 512 + ch * 16,
                g_hp + ((long long)(mtile0 + mtl) * K16 + ktb + ktl) * 256 + ch * 8);
        }
#pragma unroll
        for (int j = 0; j < 4; j++) {
            int c = j * 256 + t;
            int tile = c >> 4, ch = c & 15;
            int ntl = tile >> 2, ktl = tile & 3;
            cpa(sA + A_BYTES + tile * 256 + ch * 16,
                g_wdp + ((long long)(ntile0 + ntl) * K16 + ktb + ktl) * 128 + ch * 8);
        }
    };

    issue(0, 0); CP_COMMIT();
    issue(1, 1); CP_COMMIT();

    int sc = 0;
    for (int kt = 0; kt < KT; ++kt) {
        CP_WAIT(1);
        __syncthreads();
        if (kt + 2 < KT) {
            int sn = sc + 2; if (sn >= NSTG) sn -= NSTG;
            issue(kt + 2, sn);
        }
        CP_COMMIT();

        const char* sp = smp + sc * STAGE;
#pragma unroll
        for (int ks = 0; ks < 4; ks++) {
            uint4 a[2];
#pragma unroll
            for (int mt = 0; mt < 2; mt++)
                a[mt] = *(const uint4*)(sp + ((wm * 2 + mt) * 4 + ks) * 512 + lane * 16);
#pragma unroll
            for (int n8 = 0; n8 < 8; n8++) {
                int slot = wn * 8 + n8;
                uint2 b = *(const uint2*)(sp + A_BYTES + (slot * 4 + ks) * 256 + lane * 8);
#pragma unroll
                for (int mt = 0; mt < 2; mt++)
                    mma_f16(acc[mt][n8], a[mt].x, a[mt].y, a[mt].z, a[mt].w, b.x, b.y);
            }
        }
        sc = sc + 1; if (sc >= NSTG) sc -= NSTG;
    }

#pragma unroll
    for (int mt = 0; mt < 2; mt++) {
#pragma unroll
        for (int n8 = 0; n8 < 8; n8++) {
            int row = m0 + wm * 32 + mt * 16 + (lane >> 2);
            int col = n0 + wn * 64 + n8 * 8 + (lane & 3) * 2;
#pragma unroll
            for (int half = 0; half < 2; half++) {
                int r = row + half * 8;
                float2 o = make_float2(acc[mt][n8][half * 2], acc[mt][n8][half * 2 + 1]);
                *(float2*)(y + (long long)r * H_DIM + col) = o;
            }
        }
    }
}

// ---------------------------------------------------------------------------
extern "C" void kernel_launch(void* const* d_in, const int* in_sizes, int n_in,
                              void* d_out, int out_size)
{
    const float* x  = (const float*)d_in[0];
    const float* wg = (const float*)d_in[1];
    const float* wu = (const float*)d_in[2];
    const float* wd = (const float*)d_in[3];
    float* y = (float*)d_out;

    cudaFuncSetAttribute(k_gateup, cudaFuncAttributeMaxDynamicSharedMemorySize, SMEM_BYTES);
    cudaFuncSetAttribute(k_down,   cudaFuncAttributeMaxDynamicSharedMemorySize, SMEM_BYTES);

    k_cvt_xA<<<(int)(((long long)(M_DIM / 16) * (H_DIM / 16) * 32) / 256), 256>>>(x);
    k_cvt_wgu<<<dim3(H_DIM / 16, I_DIM / 64, 2), 256>>>(wg, wu);
    k_cvt_wd<<<dim3(I_DIM / 16, H_DIM / 64), 256>>>(wd);

    const int grid1 = (M_DIM / 128) * (I_DIM / 64);    // 11008
    const int grid2 = (M_DIM / 128) * (H_DIM / 128);   // 2048
    k_gateup<<<grid1, 256, SMEM_BYTES>>>();
    k_down<<<grid2, 256, SMEM_BYTES>>>(y);
}

// round 15
// speedup vs baseline: 1.0953x; 1.0001x over previous
#include <cuda_runtime.h>
#include <cuda_fp16.h>
#include <math.h>
#include <stdint.h>

#define M_DIM 8192
#define H_DIM 4096
#define I_DIM 11008

// Fragment-packed f16 operands.
// A-pack: [mTile16][kTile16][lane32][8 halves]  (PTX m16n8k16 A frag: a0,a1,a2,a3)
// B-pack: [nTile8][kTile16][lane32][4 halves]   (PTX m16n8k16 B frag: b0,b1)
__device__ unsigned short g_xp [(size_t)M_DIM * H_DIM];   // x  A-pack (K=H)
__device__ unsigned short g_wgp[(size_t)I_DIM * H_DIM];   // wg^T B-pack
__device__ unsigned short g_wup[(size_t)I_DIM * H_DIM];   // wu^T B-pack
__device__ unsigned short g_wdp[(size_t)H_DIM * I_DIM];   // wd^T B-pack
__device__ unsigned short g_hp [(size_t)M_DIM * I_DIM];   // h  A-pack (K=I)

__device__ __forceinline__ uint32_t pkh(float a, float b) {
    __half2 h = __floats2half2_rn(a, b);   // low = a, high = b
    return *(uint32_t*)&h;
}
__device__ __forceinline__ void mma_f16(float* c, uint32_t a0, uint32_t a1, uint32_t a2,
                                        uint32_t a3, uint32_t b0, uint32_t b1) {
    asm volatile(
        "mma.sync.aligned.m16n8k16.row.col.f32.f16.f16.f32 "
        "{%0,%1,%2,%3}, {%4,%5,%6,%7}, {%8,%9}, {%0,%1,%2,%3};"
        : "+f"(c[0]), "+f"(c[1]), "+f"(c[2]), "+f"(c[3])
        : "r"(a0), "r"(a1), "r"(a2), "r"(a3), "r"(b0), "r"(b1));
}
__device__ __forceinline__ uint32_t smem_u32(const void* p) {
    uint32_t a;
    asm("{ .reg .u64 t; cvta.to.shared.u64 t, %1; cvt.u32.u64 %0, t; }" : "=r"(a) : "l"(p));
    return a;
}
__device__ __forceinline__ void cpa(uint32_t dst, const void* src) {
    asm volatile("cp.async.cg.shared.global [%0], [%1], 16;" :: "r"(dst), "l"(src));
}
#define CP_COMMIT() asm volatile("cp.async.commit_group;" ::: "memory")
#define CP_WAIT(n)  asm volatile("cp.async.wait_group %0;" :: "n"(n) : "memory")

// stage: A 32 tiles (8mt x 4kt) x 512B = 16KB, B 64 tiles x 256B = 16KB. BK=64.
#define A_BYTES 16384
#define STAGE 32768
#define NSTG 3
#define SMEM_BYTES (NSTG * STAGE)   // 98304

// ---------------------------------------------------------------------------
// Convert kernels (once per call; DRAM-bound)
// ---------------------------------------------------------------------------
// x [M,K] row-major -> f16 A-pack
__global__ __launch_bounds__(256)
void k_cvt_xA(const float* __restrict__ x)
{
    long long g = (long long)blockIdx.x * 256 + threadIdx.x;
    long long tile = g >> 5;
    int lane = (int)(g & 31);
    const int K16 = H_DIM / 16;
    int mt = (int)(tile / K16), kt = (int)(tile % K16);
    long long r = mt * 16 + (lane >> 2);
    int k = kt * 16 + (lane & 3) * 2;
    float2 v00 = *(const float2*)(x + r * H_DIM + k);
    float2 v01 = *(const float2*)(x + r * H_DIM + k + 8);
    float2 v10 = *(const float2*)(x + (r + 8) * H_DIM + k);
    float2 v11 = *(const float2*)(x + (r + 8) * H_DIM + k + 8);
    uint4 o;
    o.x = pkh(v00.x, v00.y);   // a0
    o.y = pkh(v10.x, v10.y);   // a1
    o.z = pkh(v01.x, v01.y);   // a2
    o.w = pkh(v11.x, v11.y);   // a3
    *(uint4*)&g_xp[tile * 256 + lane * 8] = o;
}

// gate+up combined: w [K,N] row-major -> B-pack [N/8][K/16][lane][2 b32]
// block 16k x 64n; blockIdx.z selects (wg -> g_wgp) or (wu -> g_wup).
__global__ __launch_bounds__(256)
void k_cvt_wgu(const float* __restrict__ wg, const float* __restrict__ wu)
{
    __shared__ float ts[16][72];
    const int t = threadIdx.x;
    const int k0 = blockIdx.x * 16, n0 = blockIdx.y * 64;
    const int K16 = H_DIM / 16;
    const float* w = blockIdx.z ? wu : wg;
    unsigned short* dst = blockIdx.z ? g_wup : g_wgp;

    {
        int row = t >> 4, c4 = t & 15;
        float4 v = *(const float4*)(w + (long long)(k0 + row) * I_DIM + n0 + c4 * 4);
        ts[row][c4 * 4 + 0] = v.x;
        ts[row][c4 * 4 + 1] = v.y;
        ts[row][c4 * 4 + 2] = v.z;
        ts[row][c4 * 4 + 3] = v.w;
    }
    __syncthreads();
    const int nt = t >> 5, lane = t & 31;
    const int c2 = (lane & 3) * 2, n = nt * 8 + (lane >> 2);
    uint2 o;
    o.x = pkh(ts[c2][n],     ts[c2 + 1][n]);
    o.y = pkh(ts[c2 + 8][n], ts[c2 + 9][n]);
    long long base = ((long long)((n0 >> 3) + nt) * K16 + blockIdx.x) * 128 + lane * 4;
    *(uint2*)&dst[base] = o;
}

// wd: [K=I, N=H] -> B-pack
__global__ __launch_bounds__(256)
void k_cvt_wd(const float* __restrict__ w)
{
    __shared__ float ts[16][72];
    const int t = threadIdx.x;
    const int k0 = blockIdx.x * 16, n0 = blockIdx.y * 64;
    const int K16 = I_DIM / 16;
    {
        int row = t >> 4, c4 = t & 15;
        float4 v = *(const float4*)(w + (long long)(k0 + row) * H_DIM + n0 + c4 * 4);
        ts[row][c4 * 4 + 0] = v.x;
        ts[row][c4 * 4 + 1] = v.y;
        ts[row][c4 * 4 + 2] = v.z;
        ts[row][c4 * 4 + 3] = v.w;
    }
    __syncthreads();
    const int nt = t >> 5, lane = t & 31;
    const int c2 = (lane & 3) * 2, n = nt * 8 + (lane >> 2);
    uint2 o;
    o.x = pkh(ts[c2][n],     ts[c2 + 1][n]);
    o.y = pkh(ts[c2 + 8][n], ts[c2 + 9][n]);
    long long base = ((long long)((n0 >> 3) + nt) * K16 + blockIdx.x) * 128 + lane * 4;
    *(uint2*)&g_wdp[base] = o;
}

// ---------------------------------------------------------------------------
// GEMM1: h = silu(x@wg)*(x@wu). CTA 128m x 64n (gate+up), BK=64. KT=64.
// 256 thr, warps 4m x 2n; warp: 32m x 32n gate + 32n up.  (R12 mainloop)
// ---------------------------------------------------------------------------
__global__ __launch_bounds__(256, 2)
void k_gateup()
{
    extern __shared__ char smp[];
    const uint32_t sbase = smem_u32(smp);

    const int t = threadIdx.x, lane = t & 31, wid = t >> 5;
    const int wm = wid & 3, wn = wid >> 2;

    const int num_pid_m = M_DIM / 128, num_pid_n = I_DIM / 64, GROUP = 16;
    int pid = blockIdx.x;
    int gsz = GROUP * num_pid_n;
    int gid = pid / gsz;
    int first = gid * GROUP;
    int gm = min(GROUP, num_pid_m - first);
    int pid_m = first + (pid % gm);
    int pid_n = (pid % gsz) / gm;
    const int m0 = pid_m * 128, n0 = pid_n * 64;

    const int K16 = H_DIM / 16;
    const int mtile0 = m0 >> 4, ntile0 = n0 >> 3;

    float acc[2][8][4];   // n8 0-3 gate, 4-7 up
#pragma unroll
    for (int i = 0; i < 2; i++)
#pragma unroll
        for (int j = 0; j < 8; j++)
#pragma unroll
            for (int k = 0; k < 4; k++) acc[i][j][k] = 0.f;

    const int KT = H_DIM / 64;   // 64

    auto issue = [&](int kt, int st) {
        const uint32_t sA = sbase + (uint32_t)st * STAGE;
        const int ktb = kt * 4;
#pragma unroll
        for (int j = 0; j < 4; j++) {   // A: 1024 16B chunks
            int c = j * 256 + t;
            int tile = c >> 5, ch = c & 31;
            int mtl = tile >> 2, ktl = tile & 3;
            cpa(sA + tile * 512 + ch * 16,
                g_xp + ((long long)(mtile0 + mtl) * K16 + ktb + ktl) * 256 + ch * 8);
        }
#pragma unroll
        for (int j = 0; j < 4; j++) {   // B: 1024 16B chunks (64 tiles x 16)
            int c = j * 256 + t;
            int tile = c >> 4, ch = c & 15;
            int slot = tile >> 2, ktl = tile & 3;
            const unsigned short* W = (slot < 8) ? g_wgp : g_wup;
            int ntl = slot & 7;
            cpa(sA + A_BYTES + tile * 256 + ch * 16,
                W + ((long long)(ntile0 + ntl) * K16 + ktb + ktl) * 128 + ch * 8);
        }
    };

    issue(0, 0); CP_COMMIT();
    issue(1, 1); CP_COMMIT();

    int sc = 0;
    for (int kt = 0; kt < KT; ++kt) {
        CP_WAIT(1);
        __syncthreads();
        if (kt + 2 < KT) {
            int sn = sc + 2; if (sn >= NSTG) sn -= NSTG;
            issue(kt + 2, sn);
        }
        CP_COMMIT();

        const char* sp = smp + sc * STAGE;
#pragma unroll
        for (int ks = 0; ks < 4; ks++) {
            uint4 a[2];
#pragma unroll
            for (int mt = 0; mt < 2; mt++)
                a[mt] = *(const uint4*)(sp + ((wm * 2 + mt) * 4 + ks) * 512 + lane * 16);
#pragma unroll
            for (int n8 = 0; n8 < 8; n8++) {
                int slot = (n8 >> 2) * 8 + wn * 4 + (n8 & 3);
                uint2 b = *(const uint2*)(sp + A_BYTES + (slot * 4 + ks) * 256 + lane * 8);
#pragma unroll
                for (int mt = 0; mt < 2; mt++)
                    mma_f16(acc[mt][n8], a[mt].x, a[mt].y, a[mt].z, a[mt].w, b.x, b.y);
            }
        }
        sc = sc + 1; if (sc >= NSTG) sc -= NSTG;
    }

    // Epilogue: h = silu(g)*u; repack to f16 A-pack via per-warp smem staging.
    __syncthreads();
    {
        float* buf = (float*)(smp + wid * 4096);   // [2 mt][16 r][32 c]
        const int r0 = lane >> 2, c0 = (lane & 3) * 2;
#pragma unroll
        for (int mt = 0; mt < 2; mt++) {
#pragma unroll
            for (int p = 0; p < 4; p++) {
                int col = p * 8 + c0;
                float g0 = acc[mt][p][0], u0 = acc[mt][p + 4][0];
                float g1 = acc[mt][p][1], u1 = acc[mt][p + 4][1];
                float g2 = acc[mt][p][2], u2 = acc[mt][p + 4][2];
                float g3 = acc[mt][p][3], u3 = acc[mt][p + 4][3];
                float h0 = g0 / (1.f + __expf(-g0)) * u0;
                float h1 = g1 / (1.f + __expf(-g1)) * u1;
                float h2 = g2 / (1.f + __expf(-g2)) * u2;
                float h3 = g3 / (1.f + __expf(-g3)) * u3;
                *(float2*)&buf[(mt * 16 + r0) * 32 + col]     = make_float2(h0, h1);
                *(float2*)&buf[(mt * 16 + r0 + 8) * 32 + col] = make_float2(h2, h3);
            }
        }
        __syncwarp();
        const int I16 = I_DIM / 16;
#pragma unroll
        for (int mt = 0; mt < 2; mt++) {
#pragma unroll
            for (int kt2 = 0; kt2 < 2; kt2++) {
                const float* tb = &buf[mt * 16 * 32];
                int r = lane >> 2, c = (lane & 3) * 2 + kt2 * 16;
                uint4 o;
                o.x = pkh(tb[r * 32 + c],           tb[r * 32 + c + 1]);
                o.y = pkh(tb[(r + 8) * 32 + c],     tb[(r + 8) * 32 + c + 1]);
                o.z = pkh(tb[r * 32 + c + 8],       tb[r * 32 + c + 9]);
                o.w = pkh(tb[(r + 8) * 32 + c + 8], tb[(r + 8) * 32 + c + 9]);
                long long Mt = (m0 + wm * 32 + mt * 16) >> 4;
                long long Kt = (n0 + wn * 32 + kt2 * 16) >> 4;
                *(uint4*)&g_hp[(Mt * I16 + Kt) * 256 + lane * 8] = o;
            }
        }
    }
}

// ---------------------------------------------------------------------------
// GEMM2: y = h @ wd. CTA 128m x 128n, BK=64, warp tile 32m x 64n. KT=172.
// ---------------------------------------------------------------------------
__global__ __launch_bounds__(256, 2)
void k_down(float* __restrict__ y)
{
    extern __shared__ char smp[];
    const uint32_t sbase = smem_u32(smp);

    const int t = threadIdx.x, lane = t & 31, wid = t >> 5;
    const int wm = wid & 3, wn = wid >> 2;

    const int num_pid_m = M_DIM / 128, num_pid_n = H_DIM / 128, GROUP = 16;
    int pid = blockIdx.x;
    int gsz = GROUP * num_pid_n;
    int gid = pid / gsz;
    int first = gid * GROUP;
    int gm = min(GROUP, num_pid_m - first);
    int pid_m = first + (pid % gm);
    int pid_n = (pid % gsz) / gm;
    const int m0 = pid_m * 128, n0 = pid_n * 128;

    const int K16 = I_DIM / 16;
    const int mtile0 = m0 >> 4, ntile0 = n0 >> 3;

    float acc[2][8][4];
#pragma unroll
    for (int i = 0; i < 2; i++)
#pragma unroll
        for (int j = 0; j < 8; j++)
#pragma unroll
            for (int k = 0; k < 4; k++) acc[i][j][k] = 0.f;

    const int KT = I_DIM / 64;   // 172

    auto issue = [&](int kt, int st) {
        const uint32_t sA = sbase + (uint32_t)st * STAGE;
        const int ktb = kt * 4;
#pragma unroll
        for (int j = 0; j < 4; j++) {
            int c = j * 256 + t;
            int tile = c >> 5, ch = c & 31;
            int mtl = tile >> 2, ktl = tile & 3;
            cpa(sA + tile * 512 + ch * 16,
                g_hp + ((long long)(mtile0 + mtl) * K16 + ktb + ktl) * 256 + ch * 8);
        }
#pragma unroll
        for (int j = 0; j < 4; j++) {
            int c = j * 256 + t;
            int tile = c >> 4, ch = c & 15;
            int ntl = tile >> 2, ktl = tile & 3;
            cpa(sA + A_BYTES + tile * 256 + ch * 16,
                g_wdp + ((long long)(ntile0 + ntl) * K16 + ktb + ktl) * 128 + ch * 8);
        }
    };

    issue(0, 0); CP_COMMIT();
    issue(1, 1); CP_COMMIT();

    int sc = 0;
    for (int kt = 0; kt < KT; ++kt) {
        CP_WAIT(1);
        __syncthreads();
        if (kt + 2 < KT) {
            int sn = sc + 2; if (sn >= NSTG) sn -= NSTG;
            issue(kt + 2, sn);
        }
        CP_COMMIT();

        const char* sp = smp + sc * STAGE;
#pragma unroll
        for (int ks = 0; ks < 4; ks++) {
            uint4 a[2];
#pragma unroll
            for (int mt = 0; mt < 2; mt++)
                a[mt] = *(const uint4*)(sp + ((wm * 2 + mt) * 4 + ks) * 512 + lane * 16);
#pragma unroll
            for (int n8 = 0; n8 < 8; n8++) {
                int slot = wn * 8 + n8;
                uint2 b = *(const uint2*)(sp + A_BYTES + (slot * 4 + ks) * 256 + lane * 8);
#pragma unroll
                for (int mt = 0; mt < 2; mt++)
                    mma_f16(acc[mt][n8], a[mt].x, a[mt].y, a[mt].z, a[mt].w, b.x, b.y);
            }
        }
        sc = sc + 1; if (sc >= NSTG) sc -= NSTG;
    }

#pragma unroll
    for (int mt = 0; mt < 2; mt++) {
#pragma unroll
        for (int n8 = 0; n8 < 8; n8++) {
            int row = m0 + wm * 32 + mt * 16 + (lane >> 2);
            int col = n0 + wn * 64 + n8 * 8 + (lane & 3) * 2;
#pragma unroll
            for (int half = 0; half < 2; half++) {
                int r = row + half * 8;
                float2 o = make_float2(acc[mt][n8][half * 2], acc[mt][n8][half * 2 + 1]);
                *(float2*)(y + (long long)r * H_DIM + col) = o;
            }
        }
    }
}

// ---------------------------------------------------------------------------
extern "C" void kernel_launch(void* const* d_in, const int* in_sizes, int n_in,
                              void* d_out, int out_size)
{
    const float* x  = (const float*)d_in[0];
    const float* wg = (const float*)d_in[1];
    const float* wu = (const float*)d_in[2];
    const float* wd = (const float*)d_in[3];
    float* y = (float*)d_out;

    cudaFuncSetAttribute(k_gateup, cudaFuncAttributeMaxDynamicSharedMemorySize, SMEM_BYTES);
    cudaFuncSetAttribute(k_down,   cudaFuncAttributeMaxDynamicSharedMemorySize, SMEM_BYTES);

    // Side stream (created once; reused on correctness + capture calls).
    static cudaStream_t s2 = nullptr;
    static cudaEvent_t evFork = nullptr, evJoin = nullptr;
    if (!s2) {
        cudaStreamCreateWithFlags(&s2, cudaStreamNonBlocking);
        cudaEventCreateWithFlags(&evFork, cudaEventDisableTiming);
        cudaEventCreateWithFlags(&evJoin, cudaEventDisableTiming);
    }

    // Main stream: x and gate/up converts (needed by k_gateup).
    k_cvt_xA<<<(int)(((long long)(M_DIM / 16) * (H_DIM / 16) * 32) / 256), 256>>>(x);
    k_cvt_wgu<<<dim3(H_DIM / 16, I_DIM / 64, 2), 256>>>(wg, wu);

    // Fork: wd convert runs concurrently with k_gateup (independent of it).
    cudaEventRecord(evFork, 0);
    cudaStreamWaitEvent(s2, evFork, 0);
    k_cvt_wd<<<dim3(I_DIM / 16, H_DIM / 64), 256, 0, s2>>>(wd);
    cudaEventRecord(evJoin, s2);

    const int grid1 = (M_DIM / 128) * (I_DIM / 64);    // 11008
    const int grid2 = (M_DIM / 128) * (H_DIM / 128);   // 2048
    k_gateup<<<grid1, 256, SMEM_BYTES>>>();

    // Join: k_down needs both g_hp (main) and g_wdp (s2).
    cudaStreamWaitEvent(0, evJoin, 0);
    k_down<<<grid2, 256, SMEM_BYTES>>>(y);
}